// round 16
// baseline (speedup 1.0000x reference)
#include <cuda_runtime.h>
#include <cuda_fp16.h>
#include <cstddef>
#include <cstdint>

// Problem constants (fixed by setup_inputs)
#define BQ   2
#define TQ   2048
#define DQ   1024
#define HQ   16
#define HDQ  64
#define ROW3 3072   // 3*DQ

// Scratch (device globals — no allocation allowed). u32 = packed fp16x2.
__device__ uint32_t g_xh [(size_t)BQ * TQ * DQ / 2]; // x fp16 (hi only)
__device__ uint32_t g_w1h[(size_t)ROW3 * DQ / 2];    // Wqkv hi
__device__ uint32_t g_w2h[(size_t)DQ * DQ / 2];      // Wout hi
__device__ uint32_t g_ah [(size_t)BQ * TQ * DQ / 2]; // attention out (fp16 hi)
// head-major [b][h][t][64] fp16 tensors for attention
__device__ __half   g_qnh[(size_t)BQ * HQ * TQ * HDQ];
__device__ __half   g_knh[(size_t)BQ * HQ * TQ * HDQ];
__device__ __half   g_vh2[(size_t)BQ * HQ * TQ * HDQ];

typedef unsigned long long ull;

__device__ __forceinline__ unsigned su32(const void* p) {
    return (unsigned)__cvta_generic_to_shared(p);
}

// ---------------------------------------------------------------------------
// Warp-level tensor-core + async-copy primitives (base-target PTX)
// ---------------------------------------------------------------------------
#define LDSM_X4(r0, r1, r2, r3, addr) \
    asm volatile("ldmatrix.sync.aligned.m8n8.x4.shared.b16 {%0,%1,%2,%3}, [%4];" \
        : "=r"(r0), "=r"(r1), "=r"(r2), "=r"(r3) : "r"(addr))

#define LDSM_X4_T(r0, r1, r2, r3, addr) \
    asm volatile("ldmatrix.sync.aligned.m8n8.x4.trans.shared.b16 {%0,%1,%2,%3}, [%4];" \
        : "=r"(r0), "=r"(r1), "=r"(r2), "=r"(r3) : "r"(addr))

#define MMAH(c, a, b0, b1) \
    asm volatile("mma.sync.aligned.m16n8k16.row.col.f32.f16.f16.f32 " \
        "{%0,%1,%2,%3}, {%4,%5,%6,%7}, {%8,%9}, {%0,%1,%2,%3};" \
        : "+f"((c)[0]), "+f"((c)[1]), "+f"((c)[2]), "+f"((c)[3]) \
        : "r"((a)[0]), "r"((a)[1]), "r"((a)[2]), "r"((a)[3]), "r"(b0), "r"(b1))

#define CP16(dst, src) \
    asm volatile("cp.async.cg.shared.global [%0], [%1], 16;" :: "r"(dst), "l"(src))
#define CP_COMMIT() asm volatile("cp.async.commit_group;" ::: "memory")
#define CP_WAIT(n)  asm volatile("cp.async.wait_group %0;" :: "n"(n) : "memory")

// pack two fp16 (from floats) into one u32 (lo = first arg)
__device__ __forceinline__ uint32_t packh2(float lo, float hi) {
    __half2 t = __halves2half2(__float2half_rn(lo), __float2half_rn(hi));
    return *reinterpret_cast<uint32_t*>(&t);
}

#define RCPA(d, a) \
    asm("rcp.approx.f32 %0, %1;" : "=f"(d) : "f"(a))

// ---------------------------------------------------------------------------
// Merged convert: x, Wqkv, Wout -> packed fp16 (hi only), single launch.
// ---------------------------------------------------------------------------
#define N_X4  ((BQ * TQ * DQ) / 4)     // 1048576
#define N_W14 ((ROW3 * DQ) / 4)        // 786432
#define N_W24 ((DQ * DQ) / 4)          // 262144

__global__ __launch_bounds__(256) void conv_all(const float* __restrict__ x,
                                                const float* __restrict__ w1,
                                                const float* __restrict__ w2,
                                                uint32_t* __restrict__ xh,
                                                uint32_t* __restrict__ w1h,
                                                uint32_t* __restrict__ w2h) {
    int i = blockIdx.x * blockDim.x + threadIdx.x;
    const float* src;
    uint32_t* dst;
    if (i < N_X4) {
        src = x; dst = xh;
    } else if (i < N_X4 + N_W14) {
        i -= N_X4; src = w1; dst = w1h;
    } else {
        i -= N_X4 + N_W14; src = w2; dst = w2h;
        if (i >= N_W24) return;
    }
    float4 f = ((const float4*)src)[i];
    dst[2 * i]     = packh2(f.x, f.y);
    dst[2 * i + 1] = packh2(f.z, f.w);
}

// ---------------------------------------------------------------------------
// GEMM smem layout (shared by both GEMM kernels)
// ---------------------------------------------------------------------------
#define RSTR 80
#define NSTG 3
#define STG1 20480
#define OFF1_BH 10240
#define GEMM1_SMEM (NSTG * STG1)

extern __shared__ unsigned char g_dsm[];

// ---------------------------------------------------------------------------
// qkv GEMM with FUSED normalize epilogue (unchanged from R15).
// ---------------------------------------------------------------------------
__global__ __launch_bounds__(256, 2) void gemm_qkv_fused(
    const uint16_t* __restrict__ Ah, const uint16_t* __restrict__ Bh,
    __half* __restrict__ qnh, __half* __restrict__ knh, __half* __restrict__ vh,
    int K) {

    const int tid  = threadIdx.x;
    const int wid  = tid >> 5;
    const int lane = tid & 31;
    const int wm   = wid & 3;
    const int wn   = wid >> 2;

    const int row0 = blockIdx.y * 128;
    const int col0 = blockIdx.x * 128;

    const int lr = (lane & 7) + ((lane >> 3) & 1) * 8;
    const int lk = (lane >> 4) * 16;

    const unsigned sb = su32(g_dsm);

    const int r0p = (tid * 2) >> 2,     s0p = (tid * 2) & 3;
    const int r1p = (tid * 2 + 1) >> 2, s1p = (tid * 2 + 1) & 3;

    auto issue = [&](int c) {
        const unsigned base = sb + (unsigned)(c % NSTG) * STG1;
        const int k0 = c * 32;
        const unsigned d0 = base + (unsigned)(r0p * RSTR + s0p * 16);
        const unsigned d1 = base + (unsigned)(r1p * RSTR + s1p * 16);
        const size_t a0 = (size_t)(row0 + r0p) * K + k0 + s0p * 8;
        const size_t a1 = (size_t)(row0 + r1p) * K + k0 + s1p * 8;
        CP16(d0, Ah + a0);
        CP16(d1, Ah + a1);
        const size_t b0 = (size_t)(col0 + r0p) * K + k0 + s0p * 8;
        const size_t b1 = (size_t)(col0 + r1p) * K + k0 + s1p * 8;
        CP16(d0 + OFF1_BH, Bh + b0);
        CP16(d1 + OFF1_BH, Bh + b1);
    };

    float acc[2][8][4];
#pragma unroll
    for (int mt = 0; mt < 2; mt++)
#pragma unroll
        for (int nt = 0; nt < 8; nt++)
#pragma unroll
            for (int e = 0; e < 4; e++) acc[mt][nt][e] = 0.0f;

    const int nchunks = K / 32;

    issue(0); CP_COMMIT();
    issue(1); CP_COMMIT();

    for (int j = 0; j < nchunks; j++) {
        CP_WAIT(1);
        __syncthreads();

        if (j + 2 < nchunks) issue(j + 2);
        CP_COMMIT();

        const unsigned base = sb + (unsigned)(j % NSTG) * STG1;
        const unsigned aH = base, bH = base + OFF1_BH;

#pragma unroll
        for (int ks = 0; ks < 2; ks++) {
            const unsigned kb = (unsigned)(ks * 32 + lk);
            uint32_t ah[2][4];
#pragma unroll
            for (int mt = 0; mt < 2; mt++) {
                const unsigned ro = (unsigned)((wm * 32 + mt * 16 + lr) * RSTR) + kb;
                LDSM_X4(ah[mt][0], ah[mt][1], ah[mt][2], ah[mt][3], aH + ro);
            }
            uint32_t bh[4][4];
#pragma unroll
            for (int np = 0; np < 4; np++) {
                const unsigned ro = (unsigned)((wn * 64 + np * 16 + lr) * RSTR) + kb;
                LDSM_X4(bh[np][0], bh[np][1], bh[np][2], bh[np][3], bH + ro);
            }
#pragma unroll
            for (int mt = 0; mt < 2; mt++)
#pragma unroll
                for (int nt = 0; nt < 8; nt++) {
                    const int np = nt >> 1, sel = nt & 1;
                    MMAH(acc[mt][nt], ah[mt], bh[np][sel], bh[np][sel + 2]);
                }
        }
    }

    // ---- fused epilogue: normalize (q,k) + fp16 head-major write ----
    const int er   = lane >> 2;
    const int ec   = (lane & 3) * 2;
    const int part = col0 >> 10;                       // 0=q, 1=k, 2=v
    const int hloc = ((col0 & 1023) >> 6) + wn;        // head 0..15
    __half* dstp = (part == 0) ? qnh : (part == 1 ? knh : vh);

#pragma unroll
    for (int mt = 0; mt < 2; mt++) {
        const int r0 = row0 + wm * 32 + mt * 16 + er;  // token (b*TQ + t)
        const int r1 = r0 + 8;
        float s0 = 1.0f, s1 = 1.0f;
        if (part < 2) {
            float ss0 = 0.0f, ss1 = 0.0f;
#pragma unroll
            for (int nt = 0; nt < 8; nt++) {
                ss0 += acc[mt][nt][0] * acc[mt][nt][0] + acc[mt][nt][1] * acc[mt][nt][1];
                ss1 += acc[mt][nt][2] * acc[mt][nt][2] + acc[mt][nt][3] * acc[mt][nt][3];
            }
            ss0 += __shfl_xor_sync(0xffffffffu, ss0, 1);
            ss0 += __shfl_xor_sync(0xffffffffu, ss0, 2);
            ss1 += __shfl_xor_sync(0xffffffffu, ss1, 1);
            ss1 += __shfl_xor_sync(0xffffffffu, ss1, 2);
            s0 = 1.0f / fmaxf(sqrtf(ss0), 1e-12f);
            s1 = 1.0f / fmaxf(sqrtf(ss1), 1e-12f);
        }
        const int b0 = r0 >> 11, t0 = r0 & (TQ - 1);
        const int b1 = r1 >> 11, t1 = r1 & (TQ - 1);
        const size_t base0 = (((size_t)(b0 * HQ + hloc)) * TQ + t0) * HDQ;
        const size_t base1 = (((size_t)(b1 * HQ + hloc)) * TQ + t1) * HDQ;
#pragma unroll
        for (int nt = 0; nt < 8; nt++) {
            const int d = nt * 8 + ec;
            *(uint32_t*)(dstp + base0 + d) = packh2(acc[mt][nt][0] * s0, acc[mt][nt][1] * s0);
            *(uint32_t*)(dstp + base1 + d) = packh2(acc[mt][nt][2] * s1, acc[mt][nt][3] * s1);
        }
    }
}

// ---------------------------------------------------------------------------
// 1-pass fp16 GEMM (fp32 output) — out projection (unchanged).
// ---------------------------------------------------------------------------
__global__ __launch_bounds__(256, 2) void gemm_f16_1p(
    const uint16_t* __restrict__ Ah, const uint16_t* __restrict__ Bh,
    float* __restrict__ C, int M, int N, int K) {

    const int tid  = threadIdx.x;
    const int wid  = tid >> 5;
    const int lane = tid & 31;
    const int wm   = wid & 3;
    const int wn   = wid >> 2;

    const int row0 = blockIdx.y * 128;
    const int col0 = blockIdx.x * 128;

    const int lr = (lane & 7) + ((lane >> 3) & 1) * 8;
    const int lk = (lane >> 4) * 16;

    const unsigned sb = su32(g_dsm);

    const int r0p = (tid * 2) >> 2,     s0p = (tid * 2) & 3;
    const int r1p = (tid * 2 + 1) >> 2, s1p = (tid * 2 + 1) & 3;

    auto issue = [&](int c) {
        const unsigned base = sb + (unsigned)(c % NSTG) * STG1;
        const int k0 = c * 32;
        const unsigned d0 = base + (unsigned)(r0p * RSTR + s0p * 16);
        const unsigned d1 = base + (unsigned)(r1p * RSTR + s1p * 16);
        const size_t a0 = (size_t)(row0 + r0p) * K + k0 + s0p * 8;
        const size_t a1 = (size_t)(row0 + r1p) * K + k0 + s1p * 8;
        CP16(d0, Ah + a0);
        CP16(d1, Ah + a1);
        const size_t b0 = (size_t)(col0 + r0p) * K + k0 + s0p * 8;
        const size_t b1 = (size_t)(col0 + r1p) * K + k0 + s1p * 8;
        CP16(d0 + OFF1_BH, Bh + b0);
        CP16(d1 + OFF1_BH, Bh + b1);
    };

    float acc[2][8][4];
#pragma unroll
    for (int mt = 0; mt < 2; mt++)
#pragma unroll
        for (int nt = 0; nt < 8; nt++)
#pragma unroll
            for (int e = 0; e < 4; e++) acc[mt][nt][e] = 0.0f;

    const int nchunks = K / 32;

    issue(0); CP_COMMIT();
    issue(1); CP_COMMIT();

    for (int j = 0; j < nchunks; j++) {
        CP_WAIT(1);
        __syncthreads();

        if (j + 2 < nchunks) issue(j + 2);
        CP_COMMIT();

        const unsigned base = sb + (unsigned)(j % NSTG) * STG1;
        const unsigned aH = base, bH = base + OFF1_BH;

#pragma unroll
        for (int ks = 0; ks < 2; ks++) {
            const unsigned kb = (unsigned)(ks * 32 + lk);
            uint32_t ah[2][4];
#pragma unroll
            for (int mt = 0; mt < 2; mt++) {
                const unsigned ro = (unsigned)((wm * 32 + mt * 16 + lr) * RSTR) + kb;
                LDSM_X4(ah[mt][0], ah[mt][1], ah[mt][2], ah[mt][3], aH + ro);
            }
            uint32_t bh[4][4];
#pragma unroll
            for (int np = 0; np < 4; np++) {
                const unsigned ro = (unsigned)((wn * 64 + np * 16 + lr) * RSTR) + kb;
                LDSM_X4(bh[np][0], bh[np][1], bh[np][2], bh[np][3], bH + ro);
            }
#pragma unroll
            for (int mt = 0; mt < 2; mt++)
#pragma unroll
                for (int nt = 0; nt < 8; nt++) {
                    const int np = nt >> 1, sel = nt & 1;
                    MMAH(acc[mt][nt], ah[mt], bh[np][sel], bh[np][sel + 2]);
                }
        }
    }

    const int er = lane >> 2;
    const int ec = (lane & 3) * 2;
#pragma unroll
    for (int mt = 0; mt < 2; mt++) {
        const int row = row0 + wm * 32 + mt * 16 + er;
#pragma unroll
        for (int nt = 0; nt < 8; nt++) {
            const int col = col0 + wn * 64 + nt * 8 + ec;
            *(float2*)(C + (size_t)row * N + col) =
                make_float2(acc[mt][nt][0], acc[mt][nt][1]);
            *(float2*)(C + (size_t)(row + 8) * N + col) =
                make_float2(acc[mt][nt][2], acc[mt][nt][3]);
        }
    }
}

// ---------------------------------------------------------------------------
// Causal yat attention, 128-query CTAs (256 threads, 8 warps x 16 rows):
// each K/V tile load + barrier serves 2x the MMA work vs 64-query CTAs.
// Per-warp causal skip: warp drops S/T/V when its queries all precede the
// key tile (exact zeros either way -> bit-identical result). Fine-grained
// S/T/V pipeline + ones-MMA denominator as in R15.
// ---------------------------------------------------------------------------
#define VR 144
#define OFF_VH (64 * VR)
#define AST (128 * VR)        // 18432 B per stage (also exactly fits Q 128xVR)
#define ATT_SMEM (2 * AST)    // 36864 B
#define ONES2 0x3C003C00u     // fp16x2 {1.0, 1.0}

__global__ __launch_bounds__(256) void yat_attn_tc(
    const __half* __restrict__ qnh,
    const __half* __restrict__ knh,
    const __half* __restrict__ vh,
    uint32_t* __restrict__ ath) {

    const int tid  = threadIdx.x;
    const int wid  = tid >> 5;     // 0..7
    const int lane = tid & 31;

    const int qt = (int)gridDim.x - 1 - (int)blockIdx.x;  // longest first
    const int h  = blockIdx.y;
    const int b  = blockIdx.z;
    const int q0 = qt * 128;

    const int lr = (lane & 7) + ((lane >> 3) & 1) * 8;
    const int lk = (lane >> 4) * 16;

    const unsigned sb = su32(g_dsm);
    const size_t headBase = ((size_t)(b * HQ + h)) * TQ;

    const int seg = tid & 7;       // 16B segment in 128B row
    const int rb  = tid >> 3;      // 0..31

    // ---- stage Q (128 rows) into buffer 0, pull A-fragments ----
#pragma unroll
    for (int i = 0; i < 4; i++) {
        const int r = rb + 32 * i;
        const size_t so = (headBase + q0 + r) * HDQ + seg * 8;
        CP16(sb + (unsigned)(r * VR + seg * 16), qnh + so);
    }
    CP_COMMIT();
    CP_WAIT(0);
    __syncthreads();

    uint32_t qfh[4][4];
#pragma unroll
    for (int kc = 0; kc < 4; kc++) {
        const unsigned ro = (unsigned)((wid * 16 + lr) * VR + kc * 32 + lk);
        LDSM_X4(qfh[kc][0], qfh[kc][1], qfh[kc][2], qfh[kc][3], sb + ro);
    }
    __syncthreads();   // Q frags pulled; both buffers free for K/V

    auto issueKV = [&](int kt) {
        const unsigned base = sb + (unsigned)(kt & 1) * AST;
        const size_t tok = headBase + (size_t)kt * 64;
#pragma unroll
        for (int i = 0; i < 2; i++) {
            const int r = rb + 32 * i;
            const size_t so = (tok + r) * HDQ + seg * 8;
            const unsigned dofs = (unsigned)(r * VR + seg * 16);
            CP16(base + dofs,          knh + so);
            CP16(base + OFF_VH + dofs, vh + so);
        }
    };

    float accO[8][4];
#pragma unroll
    for (int nt = 0; nt < 8; nt++)
#pragma unroll
        for (int e = 0; e < 4; e++) accO[nt][e] = 0.0f;
    float accD[4] = {0.0f, 0.0f, 0.0f, 0.0f};

    const int qwlo = q0 + wid * 16;             // warp's lowest query row
    const int qg0  = qwlo + (lane >> 2);        // this thread's query row (er)

    const int nkt = 2 * qt + 2;                 // key tiles 0..2qt+1
    issueKV(0); CP_COMMIT();

    for (int kt = 0; kt < nkt; kt++) {
        CP_WAIT(0);
        __syncthreads();   // tile kt visible; all warps done with buffer kt&1

        if (kt + 1 < nkt) issueKV(kt + 1);
        CP_COMMIT();

        const int k0 = kt * 64;
        if (k0 > qwlo + 15) continue;   // warp fully masked: contributes zeros

        const unsigned base = sb + (unsigned)(kt & 1) * AST;
        const unsigned kH = base, vHb = base + OFF_VH;
        const bool diag = (k0 + 63 > qwlo);

        // S(g): S fragments for key group g (keys 16g..16g+15)
        auto S_group = [&](int g, float (&sfg)[2][4]) {
#pragma unroll
            for (int half = 0; half < 2; half++)
#pragma unroll
                for (int e = 0; e < 4; e++) sfg[half][e] = 0.0f;
#pragma unroll
            for (int kc = 0; kc < 4; kc++) {
                uint32_t khf[4];
                const unsigned ro = (unsigned)((g * 16 + lr) * VR + kc * 32 + lk);
                LDSM_X4(khf[0], khf[1], khf[2], khf[3], kH + ro);
                MMAH(sfg[0], qfh[kc], khf[0], khf[2]);
                MMAH(sfg[1], qfh[kc], khf[1], khf[3]);
            }
        };

        // T(g): transform S -> packed fp16 w A-fragment
        auto T_group = [&](int g, const float (&sfg)[2][4], uint32_t (&ah)[4]) {
#pragma unroll
            for (int half = 0; half < 2; half++) {
                float w[4];
#pragma unroll
                for (int e = 0; e < 4; e++) {
                    const float d = sfg[half][e];
                    const float den = fmaxf(fmaf(-2.0f, d, 2.01f), 1e-6f);
                    float rc; RCPA(rc, den);
                    w[e] = d * d * rc;
                }
                if (diag) {
                    const int kg = k0 + (2 * g + half) * 8 + 2 * (lane & 3);
                    if (kg     > qg0)     w[0] = 0.0f;
                    if (kg + 1 > qg0)     w[1] = 0.0f;
                    if (kg     > qg0 + 8) w[2] = 0.0f;
                    if (kg + 1 > qg0 + 8) w[3] = 0.0f;
                }
                ah[2 * half]     = packh2(w[0], w[1]);
                ah[2 * half + 1] = packh2(w[2], w[3]);
            }
        };

        // V(g): O += w@V over this key group + denominator ones-MMA
        auto V_group = [&](int g, const uint32_t (&ah)[4]) {
#pragma unroll
            for (int og = 0; og < 4; og++) {
                uint32_t vhf[4];
                const unsigned ro = (unsigned)((g * 16 + lr) * VR + og * 32 + lk);
                LDSM_X4_T(vhf[0], vhf[1], vhf[2], vhf[3], vHb + ro);
                MMAH(accO[2 * og],     ah, vhf[0], vhf[1]);
                MMAH(accO[2 * og + 1], ah, vhf[2], vhf[3]);
            }
            MMAH(accD, ah, ONES2, ONES2);
        };

        float sfA[2][4], sfB[2][4];
        uint32_t ahA[4], ahB[4];
        S_group(0, sfA);
        S_group(1, sfB);
        T_group(0, sfA, ahA);
        V_group(0, ahA);
        S_group(2, sfA);
        T_group(1, sfB, ahB);
        V_group(1, ahB);
        S_group(3, sfB);
        T_group(2, sfA, ahA);
        V_group(2, ahA);
        T_group(3, sfB, ahB);
        V_group(3, ahB);
        // no end-of-loop sync: next iteration's barrier provides the ordering
    }

    // ---- epilogue: divide by den (row sums live in accD), write fp16 hi ----
    float inv0, inv1;
    RCPA(inv0, accD[0] + 1e-6f);
    RCPA(inv1, accD[2] + 1e-6f);

    const size_t rowg  = (size_t)(b * TQ) + q0 + wid * 16 + (lane >> 2);
    const int    colb2 = h * (HDQ / 2) + (lane & 3);
#pragma unroll
    for (int nt = 0; nt < 8; nt++) {
        ath[rowg * (DQ / 2) + colb2 + nt * 4] =
            packh2(accO[nt][0] * inv0, accO[nt][1] * inv0);
        ath[(rowg + 8) * (DQ / 2) + colb2 + nt * 4] =
            packh2(accO[nt][2] * inv1, accO[nt][3] * inv1);
    }
}

// ---------------------------------------------------------------------------
// kernel_launch
// ---------------------------------------------------------------------------
extern "C" void kernel_launch(void* const* d_in, const int* in_sizes, int n_in,
                              void* d_out, int out_size) {
    (void)in_sizes; (void)n_in; (void)out_size;
    const float* x    = (const float*)d_in[0];   // [B,T,D]
    const float* Wqkv = (const float*)d_in[1];   // [3D, D]
    const float* Wout = (const float*)d_in[2];   // [D, D]
    float* out = (float*)d_out;                  // [B,T,D]

    void *p_xh, *p_w1h, *p_w2h, *p_ah;
    void *p_qnh, *p_knh, *p_vh;
    cudaGetSymbolAddress(&p_xh, g_xh);
    cudaGetSymbolAddress(&p_w1h, g_w1h); cudaGetSymbolAddress(&p_w2h, g_w2h);
    cudaGetSymbolAddress(&p_ah, g_ah);
    cudaGetSymbolAddress(&p_qnh, g_qnh);
    cudaGetSymbolAddress(&p_knh, g_knh);
    cudaGetSymbolAddress(&p_vh, g_vh2);

    static bool attr_done = false;
    if (!attr_done) {
        cudaFuncSetAttribute(gemm_qkv_fused,
                             cudaFuncAttributeMaxDynamicSharedMemorySize, GEMM1_SMEM);
        cudaFuncSetAttribute(gemm_f16_1p,
                             cudaFuncAttributeMaxDynamicSharedMemorySize, GEMM1_SMEM);
        cudaFuncSetAttribute(yat_attn_tc,
                             cudaFuncAttributeMaxDynamicSharedMemorySize, ATT_SMEM);
        attr_done = true;
    }

    const int M = BQ * TQ;  // 4096

    // 0) convert all fp32 inputs to fp16 in one launch
    const int ntot = N_X4 + N_W14 + N_W24;
    conv_all<<<(ntot + 255) / 256, 256>>>(x, Wqkv, Wout,
        (uint32_t*)p_xh, (uint32_t*)p_w1h, (uint32_t*)p_w2h);

    // 1) qkv GEMM with fused normalize + fp16 head-major epilogue
    gemm_qkv_fused<<<dim3(ROW3 / 128, M / 128), 256, GEMM1_SMEM>>>(
        (const uint16_t*)p_xh, (const uint16_t*)p_w1h,
        (__half*)p_qnh, (__half*)p_knh, (__half*)p_vh, DQ);

    // 2) causal yat attention (128-query CTAs, pipelined S/T/V) -> fp16 att
    yat_attn_tc<<<dim3(TQ / 128, HQ, BQ), 256, ATT_SMEM>>>(
        (const __half*)p_qnh, (const __half*)p_knh, (const __half*)p_vh,
        (uint32_t*)p_ah);

    // 3) out = att @ Wout^T : [4096,1024]  (fp16 1-pass)
    gemm_f16_1p<<<dim3(DQ / 128, M / 128), 256, GEMM1_SMEM>>>(
        (const uint16_t*)p_ah, (const uint16_t*)p_w2h,
        out, M, DQ, DQ);
}

// round 17
// speedup vs baseline: 1.0429x; 1.0429x over previous
#include <cuda_runtime.h>
#include <cuda_fp16.h>
#include <cstddef>
#include <cstdint>

// Problem constants (fixed by setup_inputs)
#define BQ   2
#define TQ   2048
#define DQ   1024
#define HQ   16
#define HDQ  64
#define ROW3 3072   // 3*DQ

// Scratch (device globals — no allocation allowed). u32 = packed fp16x2.
__device__ uint32_t g_xh [(size_t)BQ * TQ * DQ / 2]; // x fp16 (hi only)
__device__ uint32_t g_w1h[(size_t)ROW3 * DQ / 2];    // Wqkv hi
__device__ uint32_t g_w2h[(size_t)DQ * DQ / 2];      // Wout hi
__device__ uint32_t g_ah [(size_t)BQ * TQ * DQ / 2]; // attention out (fp16 hi)
// head-major [b][h][t][64] fp16 tensors for attention
__device__ __half   g_qnh[(size_t)BQ * HQ * TQ * HDQ];
__device__ __half   g_knh[(size_t)BQ * HQ * TQ * HDQ];
__device__ __half   g_vh2[(size_t)BQ * HQ * TQ * HDQ];

typedef unsigned long long ull;

__device__ __forceinline__ unsigned su32(const void* p) {
    return (unsigned)__cvta_generic_to_shared(p);
}

// ---------------------------------------------------------------------------
// Warp-level tensor-core + async-copy primitives (base-target PTX)
// ---------------------------------------------------------------------------
#define LDSM_X4(r0, r1, r2, r3, addr) \
    asm volatile("ldmatrix.sync.aligned.m8n8.x4.shared.b16 {%0,%1,%2,%3}, [%4];" \
        : "=r"(r0), "=r"(r1), "=r"(r2), "=r"(r3) : "r"(addr))

#define LDSM_X4_T(r0, r1, r2, r3, addr) \
    asm volatile("ldmatrix.sync.aligned.m8n8.x4.trans.shared.b16 {%0,%1,%2,%3}, [%4];" \
        : "=r"(r0), "=r"(r1), "=r"(r2), "=r"(r3) : "r"(addr))

#define MMAH(c, a, b0, b1) \
    asm volatile("mma.sync.aligned.m16n8k16.row.col.f32.f16.f16.f32 " \
        "{%0,%1,%2,%3}, {%4,%5,%6,%7}, {%8,%9}, {%0,%1,%2,%3};" \
        : "+f"((c)[0]), "+f"((c)[1]), "+f"((c)[2]), "+f"((c)[3]) \
        : "r"((a)[0]), "r"((a)[1]), "r"((a)[2]), "r"((a)[3]), "r"(b0), "r"(b1))

#define CP16(dst, src) \
    asm volatile("cp.async.cg.shared.global [%0], [%1], 16;" :: "r"(dst), "l"(src))
#define CP_COMMIT() asm volatile("cp.async.commit_group;" ::: "memory")
#define CP_WAIT(n)  asm volatile("cp.async.wait_group %0;" :: "n"(n) : "memory")

// pack two fp16 (from floats) into one u32 (lo = first arg)
__device__ __forceinline__ uint32_t packh2(float lo, float hi) {
    __half2 t = __halves2half2(__float2half_rn(lo), __float2half_rn(hi));
    return *reinterpret_cast<uint32_t*>(&t);
}

#define RCPA(d, a) \
    asm("rcp.approx.f32 %0, %1;" : "=f"(d) : "f"(a))

// ---------------------------------------------------------------------------
// Merged convert: x, Wqkv, Wout -> packed fp16 (hi only), single launch.
// ---------------------------------------------------------------------------
#define N_X4  ((BQ * TQ * DQ) / 4)     // 1048576
#define N_W14 ((ROW3 * DQ) / 4)        // 786432
#define N_W24 ((DQ * DQ) / 4)          // 262144

__global__ __launch_bounds__(256) void conv_all(const float* __restrict__ x,
                                                const float* __restrict__ w1,
                                                const float* __restrict__ w2,
                                                uint32_t* __restrict__ xh,
                                                uint32_t* __restrict__ w1h,
                                                uint32_t* __restrict__ w2h) {
    int i = blockIdx.x * blockDim.x + threadIdx.x;
    const float* src;
    uint32_t* dst;
    if (i < N_X4) {
        src = x; dst = xh;
    } else if (i < N_X4 + N_W14) {
        i -= N_X4; src = w1; dst = w1h;
    } else {
        i -= N_X4 + N_W14; src = w2; dst = w2h;
        if (i >= N_W24) return;
    }
    float4 f = ((const float4*)src)[i];
    dst[2 * i]     = packh2(f.x, f.y);
    dst[2 * i + 1] = packh2(f.z, f.w);
}

// ---------------------------------------------------------------------------
// GEMM smem layout: 4-stage cp.async pipeline (80 KB, 2 CTAs/SM)
// ---------------------------------------------------------------------------
#define RSTR 80
#define NSTG 4
#define STG1 20480
#define OFF1_BH 10240
#define GEMM1_SMEM (NSTG * STG1)

extern __shared__ unsigned char g_dsm[];

// ---------------------------------------------------------------------------
// qkv GEMM with FUSED normalize epilogue (R15 logic, 4-stage pipeline).
// ---------------------------------------------------------------------------
__global__ __launch_bounds__(256, 2) void gemm_qkv_fused(
    const uint16_t* __restrict__ Ah, const uint16_t* __restrict__ Bh,
    __half* __restrict__ qnh, __half* __restrict__ knh, __half* __restrict__ vh,
    int K) {

    const int tid  = threadIdx.x;
    const int wid  = tid >> 5;
    const int lane = tid & 31;
    const int wm   = wid & 3;
    const int wn   = wid >> 2;

    const int row0 = blockIdx.y * 128;
    const int col0 = blockIdx.x * 128;

    const int lr = (lane & 7) + ((lane >> 3) & 1) * 8;
    const int lk = (lane >> 4) * 16;

    const unsigned sb = su32(g_dsm);

    const int r0p = (tid * 2) >> 2,     s0p = (tid * 2) & 3;
    const int r1p = (tid * 2 + 1) >> 2, s1p = (tid * 2 + 1) & 3;

    auto issue = [&](int c) {
        const unsigned base = sb + (unsigned)(c % NSTG) * STG1;
        const int k0 = c * 32;
        const unsigned d0 = base + (unsigned)(r0p * RSTR + s0p * 16);
        const unsigned d1 = base + (unsigned)(r1p * RSTR + s1p * 16);
        const size_t a0 = (size_t)(row0 + r0p) * K + k0 + s0p * 8;
        const size_t a1 = (size_t)(row0 + r1p) * K + k0 + s1p * 8;
        CP16(d0, Ah + a0);
        CP16(d1, Ah + a1);
        const size_t b0 = (size_t)(col0 + r0p) * K + k0 + s0p * 8;
        const size_t b1 = (size_t)(col0 + r1p) * K + k0 + s1p * 8;
        CP16(d0 + OFF1_BH, Bh + b0);
        CP16(d1 + OFF1_BH, Bh + b1);
    };

    float acc[2][8][4];
#pragma unroll
    for (int mt = 0; mt < 2; mt++)
#pragma unroll
        for (int nt = 0; nt < 8; nt++)
#pragma unroll
            for (int e = 0; e < 4; e++) acc[mt][nt][e] = 0.0f;

    const int nchunks = K / 32;

    issue(0); CP_COMMIT();
    issue(1); CP_COMMIT();
    issue(2); CP_COMMIT();

    for (int j = 0; j < nchunks; j++) {
        CP_WAIT(2);            // group j complete (<=2 newer outstanding)
        __syncthreads();       // all threads done with buffer being overwritten

        if (j + 3 < nchunks) issue(j + 3);
        CP_COMMIT();           // always commit (group accounting)

        const unsigned base = sb + (unsigned)(j % NSTG) * STG1;
        const unsigned aH = base, bH = base + OFF1_BH;

#pragma unroll
        for (int ks = 0; ks < 2; ks++) {
            const unsigned kb = (unsigned)(ks * 32 + lk);
            uint32_t ah[2][4];
#pragma unroll
            for (int mt = 0; mt < 2; mt++) {
                const unsigned ro = (unsigned)((wm * 32 + mt * 16 + lr) * RSTR) + kb;
                LDSM_X4(ah[mt][0], ah[mt][1], ah[mt][2], ah[mt][3], aH + ro);
            }
            uint32_t bh[4][4];
#pragma unroll
            for (int np = 0; np < 4; np++) {
                const unsigned ro = (unsigned)((wn * 64 + np * 16 + lr) * RSTR) + kb;
                LDSM_X4(bh[np][0], bh[np][1], bh[np][2], bh[np][3], bH + ro);
            }
#pragma unroll
            for (int mt = 0; mt < 2; mt++)
#pragma unroll
                for (int nt = 0; nt < 8; nt++) {
                    const int np = nt >> 1, sel = nt & 1;
                    MMAH(acc[mt][nt], ah[mt], bh[np][sel], bh[np][sel + 2]);
                }
        }
    }

    // ---- fused epilogue: normalize (q,k) + fp16 head-major write ----
    const int er   = lane >> 2;
    const int ec   = (lane & 3) * 2;
    const int part = col0 >> 10;                       // 0=q, 1=k, 2=v
    const int hloc = ((col0 & 1023) >> 6) + wn;        // head 0..15
    __half* dstp = (part == 0) ? qnh : (part == 1 ? knh : vh);

#pragma unroll
    for (int mt = 0; mt < 2; mt++) {
        const int r0 = row0 + wm * 32 + mt * 16 + er;  // token (b*TQ + t)
        const int r1 = r0 + 8;
        float s0 = 1.0f, s1 = 1.0f;
        if (part < 2) {
            float ss0 = 0.0f, ss1 = 0.0f;
#pragma unroll
            for (int nt = 0; nt < 8; nt++) {
                ss0 += acc[mt][nt][0] * acc[mt][nt][0] + acc[mt][nt][1] * acc[mt][nt][1];
                ss1 += acc[mt][nt][2] * acc[mt][nt][2] + acc[mt][nt][3] * acc[mt][nt][3];
            }
            ss0 += __shfl_xor_sync(0xffffffffu, ss0, 1);
            ss0 += __shfl_xor_sync(0xffffffffu, ss0, 2);
            ss1 += __shfl_xor_sync(0xffffffffu, ss1, 1);
            ss1 += __shfl_xor_sync(0xffffffffu, ss1, 2);
            s0 = 1.0f / fmaxf(sqrtf(ss0), 1e-12f);
            s1 = 1.0f / fmaxf(sqrtf(ss1), 1e-12f);
        }
        const int b0 = r0 >> 11, t0 = r0 & (TQ - 1);
        const int b1 = r1 >> 11, t1 = r1 & (TQ - 1);
        const size_t base0 = (((size_t)(b0 * HQ + hloc)) * TQ + t0) * HDQ;
        const size_t base1 = (((size_t)(b1 * HQ + hloc)) * TQ + t1) * HDQ;
#pragma unroll
        for (int nt = 0; nt < 8; nt++) {
            const int d = nt * 8 + ec;
            *(uint32_t*)(dstp + base0 + d) = packh2(acc[mt][nt][0] * s0, acc[mt][nt][1] * s0);
            *(uint32_t*)(dstp + base1 + d) = packh2(acc[mt][nt][2] * s1, acc[mt][nt][3] * s1);
        }
    }
}

// ---------------------------------------------------------------------------
// 1-pass fp16 GEMM (fp32 output) — out projection, 4-stage pipeline.
// ---------------------------------------------------------------------------
__global__ __launch_bounds__(256, 2) void gemm_f16_1p(
    const uint16_t* __restrict__ Ah, const uint16_t* __restrict__ Bh,
    float* __restrict__ C, int M, int N, int K) {

    const int tid  = threadIdx.x;
    const int wid  = tid >> 5;
    const int lane = tid & 31;
    const int wm   = wid & 3;
    const int wn   = wid >> 2;

    const int row0 = blockIdx.y * 128;
    const int col0 = blockIdx.x * 128;

    const int lr = (lane & 7) + ((lane >> 3) & 1) * 8;
    const int lk = (lane >> 4) * 16;

    const unsigned sb = su32(g_dsm);

    const int r0p = (tid * 2) >> 2,     s0p = (tid * 2) & 3;
    const int r1p = (tid * 2 + 1) >> 2, s1p = (tid * 2 + 1) & 3;

    auto issue = [&](int c) {
        const unsigned base = sb + (unsigned)(c % NSTG) * STG1;
        const int k0 = c * 32;
        const unsigned d0 = base + (unsigned)(r0p * RSTR + s0p * 16);
        const unsigned d1 = base + (unsigned)(r1p * RSTR + s1p * 16);
        const size_t a0 = (size_t)(row0 + r0p) * K + k0 + s0p * 8;
        const size_t a1 = (size_t)(row0 + r1p) * K + k0 + s1p * 8;
        CP16(d0, Ah + a0);
        CP16(d1, Ah + a1);
        const size_t b0 = (size_t)(col0 + r0p) * K + k0 + s0p * 8;
        const size_t b1 = (size_t)(col0 + r1p) * K + k0 + s1p * 8;
        CP16(d0 + OFF1_BH, Bh + b0);
        CP16(d1 + OFF1_BH, Bh + b1);
    };

    float acc[2][8][4];
#pragma unroll
    for (int mt = 0; mt < 2; mt++)
#pragma unroll
        for (int nt = 0; nt < 8; nt++)
#pragma unroll
            for (int e = 0; e < 4; e++) acc[mt][nt][e] = 0.0f;

    const int nchunks = K / 32;

    issue(0); CP_COMMIT();
    issue(1); CP_COMMIT();
    issue(2); CP_COMMIT();

    for (int j = 0; j < nchunks; j++) {
        CP_WAIT(2);
        __syncthreads();

        if (j + 3 < nchunks) issue(j + 3);
        CP_COMMIT();

        const unsigned base = sb + (unsigned)(j % NSTG) * STG1;
        const unsigned aH = base, bH = base + OFF1_BH;

#pragma unroll
        for (int ks = 0; ks < 2; ks++) {
            const unsigned kb = (unsigned)(ks * 32 + lk);
            uint32_t ah[2][4];
#pragma unroll
            for (int mt = 0; mt < 2; mt++) {
                const unsigned ro = (unsigned)((wm * 32 + mt * 16 + lr) * RSTR) + kb;
                LDSM_X4(ah[mt][0], ah[mt][1], ah[mt][2], ah[mt][3], aH + ro);
            }
            uint32_t bh[4][4];
#pragma unroll
            for (int np = 0; np < 4; np++) {
                const unsigned ro = (unsigned)((wn * 64 + np * 16 + lr) * RSTR) + kb;
                LDSM_X4(bh[np][0], bh[np][1], bh[np][2], bh[np][3], bH + ro);
            }
#pragma unroll
            for (int mt = 0; mt < 2; mt++)
#pragma unroll
                for (int nt = 0; nt < 8; nt++) {
                    const int np = nt >> 1, sel = nt & 1;
                    MMAH(acc[mt][nt], ah[mt], bh[np][sel], bh[np][sel + 2]);
                }
        }
    }

    const int er = lane >> 2;
    const int ec = (lane & 3) * 2;
#pragma unroll
    for (int mt = 0; mt < 2; mt++) {
        const int row = row0 + wm * 32 + mt * 16 + er;
#pragma unroll
        for (int nt = 0; nt < 8; nt++) {
            const int col = col0 + wn * 64 + nt * 8 + ec;
            *(float2*)(C + (size_t)row * N + col) =
                make_float2(acc[mt][nt][0], acc[mt][nt][1]);
            *(float2*)(C + (size_t)(row + 8) * N + col) =
                make_float2(acc[mt][nt][2], acc[mt][nt][3]);
        }
    }
}

// ---------------------------------------------------------------------------
// Causal yat attention (R15 64-query structure, 3-stage KV pipeline):
// per key tile, fine-grained S/T/V schedule + ones-MMA denominator.
// ---------------------------------------------------------------------------
#define VR 144
#define OFF_VH (64 * VR)
#define AST (128 * VR)        // 18432 B per stage
#define ANSTG 3
#define ATT_SMEM (ANSTG * AST)  // 55296 B
#define ONES2 0x3C003C00u     // fp16x2 {1.0, 1.0}

__global__ __launch_bounds__(128) void yat_attn_tc(
    const __half* __restrict__ qnh,
    const __half* __restrict__ knh,
    const __half* __restrict__ vh,
    uint32_t* __restrict__ ath) {

    const int tid  = threadIdx.x;
    const int wid  = tid >> 5;
    const int lane = tid & 31;

    const int qt = (int)gridDim.x - 1 - (int)blockIdx.x;  // longest first
    const int h  = blockIdx.y;
    const int b  = blockIdx.z;
    const int q0 = qt * 64;

    const int lr = (lane & 7) + ((lane >> 3) & 1) * 8;
    const int lk = (lane >> 4) * 16;

    const unsigned sb = su32(g_dsm);
    const size_t headBase = ((size_t)(b * HQ + h)) * TQ;

    const int seg = tid & 7;
    const int rb  = tid >> 3;

    // ---- stage Q (hi) into buffer 0, pull A-fragments ----
#pragma unroll
    for (int i = 0; i < 4; i++) {
        const int r = rb + 16 * i;
        const size_t so = (headBase + q0 + r) * HDQ + seg * 8;
        CP16(sb + (unsigned)(r * VR + seg * 16), qnh + so);
    }
    CP_COMMIT();
    CP_WAIT(0);
    __syncthreads();

    uint32_t qfh[4][4];
#pragma unroll
    for (int kc = 0; kc < 4; kc++) {
        const unsigned ro = (unsigned)((wid * 16 + lr) * VR + kc * 32 + lk);
        LDSM_X4(qfh[kc][0], qfh[kc][1], qfh[kc][2], qfh[kc][3], sb + ro);
    }
    __syncthreads();   // Q frags pulled; buffers free for K/V

    auto issueKV = [&](int kt) {
        const unsigned base = sb + (unsigned)(kt % ANSTG) * AST;
        const size_t tok = headBase + (size_t)kt * 64;
#pragma unroll
        for (int i = 0; i < 4; i++) {
            const int r = rb + 16 * i;
            const size_t so = (tok + r) * HDQ + seg * 8;
            const unsigned dofs = (unsigned)(r * VR + seg * 16);
            CP16(base + dofs,          knh + so);
            CP16(base + OFF_VH + dofs, vh + so);
        }
    };

    float accO[8][4];
#pragma unroll
    for (int nt = 0; nt < 8; nt++)
#pragma unroll
        for (int e = 0; e < 4; e++) accO[nt][e] = 0.0f;
    float accD[4] = {0.0f, 0.0f, 0.0f, 0.0f};

    const int qg0 = q0 + wid * 16 + (lane >> 2);

    issueKV(0); CP_COMMIT();
    if (qt >= 1) issueKV(1);
    CP_COMMIT();

    for (int kt = 0; kt <= qt; kt++) {
        CP_WAIT(1);        // tile kt complete (<=1 newer group outstanding)
        __syncthreads();   // all warps done with the buffer being refilled

        if (kt + 2 <= qt) issueKV(kt + 2);
        CP_COMMIT();       // always commit (group accounting)

        const unsigned base = sb + (unsigned)(kt % ANSTG) * AST;
        const unsigned kH = base, vHb = base + OFF_VH;
        const bool diag = (kt == qt);

        // S(g): S fragments for key group g (keys 16g..16g+15)
        auto S_group = [&](int g, float (&sfg)[2][4]) {
#pragma unroll
            for (int half = 0; half < 2; half++)
#pragma unroll
                for (int e = 0; e < 4; e++) sfg[half][e] = 0.0f;
#pragma unroll
            for (int kc = 0; kc < 4; kc++) {
                uint32_t khf[4];
                const unsigned ro = (unsigned)((g * 16 + lr) * VR + kc * 32 + lk);
                LDSM_X4(khf[0], khf[1], khf[2], khf[3], kH + ro);
                MMAH(sfg[0], qfh[kc], khf[0], khf[2]);
                MMAH(sfg[1], qfh[kc], khf[1], khf[3]);
            }
        };

        // T(g): transform S -> packed fp16 w A-fragment
        auto T_group = [&](int g, const float (&sfg)[2][4], uint32_t (&ah)[4]) {
#pragma unroll
            for (int half = 0; half < 2; half++) {
                float w[4];
#pragma unroll
                for (int e = 0; e < 4; e++) {
                    const float d = sfg[half][e];
                    const float den = fmaxf(fmaf(-2.0f, d, 2.01f), 1e-6f);
                    float rc; RCPA(rc, den);
                    w[e] = d * d * rc;
                }
                if (diag) {
                    const int kg = kt * 64 + (2 * g + half) * 8 + 2 * (lane & 3);
                    if (kg     > qg0)     w[0] = 0.0f;
                    if (kg + 1 > qg0)     w[1] = 0.0f;
                    if (kg     > qg0 + 8) w[2] = 0.0f;
                    if (kg + 1 > qg0 + 8) w[3] = 0.0f;
                }
                ah[2 * half]     = packh2(w[0], w[1]);
                ah[2 * half + 1] = packh2(w[2], w[3]);
            }
        };

        // V(g): O += w@V over this key group + denominator ones-MMA
        auto V_group = [&](int g, const uint32_t (&ah)[4]) {
#pragma unroll
            for (int og = 0; og < 4; og++) {
                uint32_t vhf[4];
                const unsigned ro = (unsigned)((g * 16 + lr) * VR + og * 32 + lk);
                LDSM_X4_T(vhf[0], vhf[1], vhf[2], vhf[3], vHb + ro);
                MMAH(accO[2 * og],     ah, vhf[0], vhf[1]);
                MMAH(accO[2 * og + 1], ah, vhf[2], vhf[3]);
            }
            MMAH(accD, ah, ONES2, ONES2);
        };

        float sfA[2][4], sfB[2][4];
        uint32_t ahA[4], ahB[4];
        S_group(0, sfA);
        S_group(1, sfB);
        T_group(0, sfA, ahA);
        V_group(0, ahA);
        S_group(2, sfA);
        T_group(1, sfB, ahB);
        V_group(1, ahB);
        S_group(3, sfB);
        T_group(2, sfA, ahA);
        V_group(2, ahA);
        T_group(3, sfB, ahB);
        V_group(3, ahB);
        // no end-of-loop sync: next iteration's barrier provides the ordering
    }

    // ---- epilogue: divide by den (row sums live in accD), write fp16 hi ----
    float inv0, inv1;
    RCPA(inv0, accD[0] + 1e-6f);
    RCPA(inv1, accD[2] + 1e-6f);

    const size_t rowg  = (size_t)(b * TQ) + q0 + wid * 16 + (lane >> 2);
    const int    colb2 = h * (HDQ / 2) + (lane & 3);
#pragma unroll
    for (int nt = 0; nt < 8; nt++) {
        ath[rowg * (DQ / 2) + colb2 + nt * 4] =
            packh2(accO[nt][0] * inv0, accO[nt][1] * inv0);
        ath[(rowg + 8) * (DQ / 2) + colb2 + nt * 4] =
            packh2(accO[nt][2] * inv1, accO[nt][3] * inv1);
    }
}

// ---------------------------------------------------------------------------
// kernel_launch
// ---------------------------------------------------------------------------
extern "C" void kernel_launch(void* const* d_in, const int* in_sizes, int n_in,
                              void* d_out, int out_size) {
    (void)in_sizes; (void)n_in; (void)out_size;
    const float* x    = (const float*)d_in[0];   // [B,T,D]
    const float* Wqkv = (const float*)d_in[1];   // [3D, D]
    const float* Wout = (const float*)d_in[2];   // [D, D]
    float* out = (float*)d_out;                  // [B,T,D]

    void *p_xh, *p_w1h, *p_w2h, *p_ah;
    void *p_qnh, *p_knh, *p_vh;
    cudaGetSymbolAddress(&p_xh, g_xh);
    cudaGetSymbolAddress(&p_w1h, g_w1h); cudaGetSymbolAddress(&p_w2h, g_w2h);
    cudaGetSymbolAddress(&p_ah, g_ah);
    cudaGetSymbolAddress(&p_qnh, g_qnh);
    cudaGetSymbolAddress(&p_knh, g_knh);
    cudaGetSymbolAddress(&p_vh, g_vh2);

    static bool attr_done = false;
    if (!attr_done) {
        cudaFuncSetAttribute(gemm_qkv_fused,
                             cudaFuncAttributeMaxDynamicSharedMemorySize, GEMM1_SMEM);
        cudaFuncSetAttribute(gemm_f16_1p,
                             cudaFuncAttributeMaxDynamicSharedMemorySize, GEMM1_SMEM);
        cudaFuncSetAttribute(yat_attn_tc,
                             cudaFuncAttributeMaxDynamicSharedMemorySize, ATT_SMEM);
        attr_done = true;
    }

    const int M = BQ * TQ;  // 4096

    // 0) convert all fp32 inputs to fp16 in one launch
    const int ntot = N_X4 + N_W14 + N_W24;
    conv_all<<<(ntot + 255) / 256, 256>>>(x, Wqkv, Wout,
        (uint32_t*)p_xh, (uint32_t*)p_w1h, (uint32_t*)p_w2h);

    // 1) qkv GEMM with fused normalize + fp16 head-major epilogue
    gemm_qkv_fused<<<dim3(ROW3 / 128, M / 128), 256, GEMM1_SMEM>>>(
        (const uint16_t*)p_xh, (const uint16_t*)p_w1h,
        (__half*)p_qnh, (__half*)p_knh, (__half*)p_vh, DQ);

    // 2) causal yat attention (64-query CTAs, 3-stage KV pipeline) -> fp16 att
    yat_attn_tc<<<dim3(TQ / 64, HQ, BQ), 128, ATT_SMEM>>>(
        (const __half*)p_qnh, (const __half*)p_knh, (const __half*)p_vh,
        (uint32_t*)p_ah);

    // 3) out = att @ Wout^T : [4096,1024]  (fp16 1-pass)
    gemm_f16_1p<<<dim3(DQ / 128, M / 128), 256, GEMM1_SMEM>>>(
        (const uint16_t*)p_ah, (const uint16_t*)p_w2h,
        out, M, DQ, DQ);
}